// round 13
// baseline (speedup 1.0000x reference)
#include <cuda_runtime.h>

#define TLEN  640
#define DDIM  256
#define NH    64              // distinct harmonics (D / NUM_CH)
#define NWARP 8               // warps per block
#define SB_PER_BLK 4          // each block: 4 sbs, 2 warps (halves) per sb
#define NTH   320             // samples per half
#define NG    (NTH / 4)       // 80 4-sample groups per warp

typedef unsigned long long u64;

__device__ __forceinline__ u64 pk2(float lo, float hi) {
    u64 r; asm("mov.b64 %0, {%1,%2};" : "=l"(r) : "f"(lo), "f"(hi)); return r;
}
__device__ __forceinline__ void upk2(u64 v, float &lo, float &hi) {
    asm("mov.b64 {%0,%1}, %2;" : "=f"(lo), "=f"(hi) : "l"(v));
}
__device__ __forceinline__ u64 fma2(u64 a, u64 b, u64 c) {
    u64 d; asm("fma.rn.f32x2 %0, %1, %2, %3;" : "=l"(d) : "l"(a), "l"(b), "l"(c)); return d;
}

#define INV2PI 0.15915494309189535f
#define PI2_HI 6.28125f                    // 8-bit mantissa: k*PI2_HI exact for k small
#define PI2_LO 1.9353071795864769e-3f
#define T_WAV  6.25e-05f                   // fl(1/16000), matches reference arange*scalar

// fast mod-2pi + MUFU sincos
__device__ __forceinline__ void fast_sincos_r(float x, float *s, float *c) {
    const float k = rintf(x * INV2PI);
    float r = __fmaf_rn(-k, PI2_HI, x);
    r = __fmaf_rn(-k, PI2_LO, r);
    __sincosf(r, s, c);
}

// Half-sb per warp: warp w -> sb_local = w>>1, half = w&1 (samples [320*half, +320)).
// 4-way decimated Goertzel (chains at angle 4*delta, 80 steps each);
// per chain y_c = s1 - e^{-iD}s2, z_c = conj(y_c);
// acc = ((z0 e^{-id} + z1) e^{-id} + z2) e^{-id} + z3;  C+iS = e^{i psiL} acc,
// psiL anchored at this half's last sample index -> halves are ADDITIVE.
// out[sb,dd] = a[dd] * ( cos(phi)*S_h + sin(phi)*C_h ),  h = dd>>2
__global__ __launch_bounds__(256) void sinenet_kernel(
    const float* __restrict__ x,   const float* __restrict__ nlf,
    const float* __restrict__ tau, const float* __restrict__ a,
    const float* __restrict__ phi, const float* __restrict__ i2pi,
    const float* __restrict__ kT,  float* __restrict__ out)
{
    __shared__ __align__(16) float xs[SB_PER_BLK * TLEN];   // 2560 floats
    __shared__ float partS[NWARP][NH], partC[NWARP][NH];

    const int tid = threadIdx.x;
    const int w   = tid >> 5;
    const int l   = tid & 31;
    const int sbl  = w >> 1;                 // sb within block
    const int half = w & 1;
    const int sb   = blockIdx.x * SB_PER_BLK + sbl;

    // cooperative staging of the block's 4 x-rows (640 float4 loads)
    {
        const float4* xg4 = reinterpret_cast<const float4*>(x + blockIdx.x * SB_PER_BLK * TLEN);
        float4* xs4 = reinterpret_cast<float4*>(xs);
        #pragma unroll
        for (int i = tid; i < SB_PER_BLK * TLEN / 4; i += 256) xs4[i] = xg4[i];
    }

    // ---- per-thread seeds, all fp32 (overlap the staging LDG latency) ----
    const float fF   = expf(__fadd_rn(__fmul_rn(nlf[sb], 0.373288f), 5.02654f));
    const float tv   = tau[sb];
    const float om1  = __fmul_rn(i2pi[0], fF);
    const int   tL   = half * NTH + (NTH - 1);            // last sample of half
    const float tshL = __fadd_rn(__fmul_rn((float)tL, T_WAV), -tv);

    // base = om1*tshL mod 2pi as hi/lo pair (exact product split + Cody-Waite)
    float bHi, bLo;
    {
        const float p  = __fmul_rn(om1, tshL);
        const float pe = __fmaf_rn(om1, tshL, -p);
        const float k  = rintf(p * INV2PI);
        float r = __fmaf_rn(-k, PI2_HI, p);
        r = __fmaf_rn(-k, PI2_LO, r);
        bHi = r;  bLo = pe;
    }

    float cd[2], sd[2], cD[2], sD[2], ce[2], se[2];
    #pragma unroll
    for (int q = 0; q < 2; ++q) {
        const int   h   = l + 32 * q;
        const float Hf  = (float)(h + 1);
        const float omg = __fmul_rn(i2pi[4 * h], fF);     // bit-matches ref's i_f
        const float dlt = omg * T_WAV;
        fast_sincos_r(dlt, &sd[q], &cd[q]);               // per-sample step
        fast_sincos_r(4.0f * dlt, &sD[q], &cD[q]);        // chain angle 4*delta
        const float eps = __fmaf_rn(-Hf, om1, omg);       // exact residual
        // psiL = Hf*(bHi+bLo) + eps*tshL, Cody-Waite reduced mod 2pi
        const float p   = Hf * bHi;
        const float pe  = __fmaf_rn(Hf, bHi, -p);
        const float plo = __fmaf_rn(Hf, bLo, __fmaf_rn(eps, tshL, pe));
        const float k   = rintf(p * INV2PI);
        float r = __fmaf_rn(-k, PI2_HI, p);
        r = __fmaf_rn(-k, PI2_LO, r) + plo;
        __sincosf(r, &se[q], &ce[q]);
    }

    const u64 twoC = pk2(cD[0] + cD[0], cD[1] + cD[1]);
    const u64 nOne = pk2(-1.0f, -1.0f);
    u64 a1 = 0ull, A2 = 0ull;   // chain 0 (samples 4u+0)
    u64 b1 = 0ull, b2 = 0ull;   // chain 1
    u64 c1 = 0ull, c2 = 0ull;   // chain 2
    u64 d1 = 0ull, d2 = 0ull;   // chain 3

    __syncthreads();   // staging visible

    // main loop: 1 LDS.128 + 4 packs + 8 FFMA2 per 4 samples; 4 indep chains
    const float4* xp = reinterpret_cast<const float4*>(xs + sbl * TLEN + half * NTH);
    #pragma unroll 4
    for (int u = 0; u < NG; ++u) {
        const float4 xv = xp[u];
        {   const u64 xq = pk2(xv.x, xv.x);
            const u64 t = fma2(nOne, A2, xq);
            const u64 n = fma2(twoC, a1, t);  A2 = a1; a1 = n; }
        {   const u64 xq = pk2(xv.y, xv.y);
            const u64 t = fma2(nOne, b2, xq);
            const u64 n = fma2(twoC, b1, t);  b2 = b1; b1 = n; }
        {   const u64 xq = pk2(xv.z, xv.z);
            const u64 t = fma2(nOne, c2, xq);
            const u64 n = fma2(twoC, c1, t);  c2 = c1; c1 = n; }
        {   const u64 xq = pk2(xv.w, xv.w);
            const u64 t = fma2(nOne, d2, xq);
            const u64 n = fma2(twoC, d1, t);  d2 = d1; d1 = n; }
    }

    // extraction + chain combine -> per-half (S,C), written to smem
    float s1f[4][2], s2f[4][2];
    upk2(a1, s1f[0][0], s1f[0][1]);  upk2(A2, s2f[0][0], s2f[0][1]);
    upk2(b1, s1f[1][0], s1f[1][1]);  upk2(b2, s2f[1][0], s2f[1][1]);
    upk2(c1, s1f[2][0], s1f[2][1]);  upk2(c2, s2f[2][0], s2f[2][1]);
    upk2(d1, s1f[3][0], s1f[3][1]);  upk2(d2, s2f[3][0], s2f[3][1]);

    #pragma unroll
    for (int q = 0; q < 2; ++q) {
        float accR = 0.0f, accI = 0.0f;
        #pragma unroll
        for (int c = 0; c < 4; ++c) {
            const float zR = __fmaf_rn(-cD[q], s2f[c][q], s1f[c][q]);
            const float zI = -sD[q] * s2f[c][q];
            if (c == 0) { accR = zR; accI = zI; }
            else {
                const float nR = __fmaf_rn(accR, cd[q],  accI * sd[q]);
                const float nI = __fmaf_rn(accI, cd[q], -accR * sd[q]);
                accR = nR + zR;
                accI = nI + zI;
            }
        }
        const float C = __fmaf_rn(ce[q], accR, -se[q] * accI);
        const float S = __fmaf_rn(se[q], accR,  ce[q] * accI);
        const int h = l + 32 * q;
        partS[w][h] = S;
        partC[w][h] = C;
    }
    __syncthreads();

    // epilogue: 256 threads = 4 sb x 64 harmonics; sum 2 halves, emit float4
    {
        const int  sl = tid >> 6;            // sb within block
        const int  h  = tid & 63;
        const int  w0 = sl * 2;
        const float Ss = partS[w0][h] + partS[w0 + 1][h];
        const float Cs = partC[w0][h] + partC[w0 + 1][h];
        const float4 a4 = reinterpret_cast<const float4*>(a)[h];
        const float4 p4 = reinterpret_cast<const float4*>(phi)[h];
        float4 o;
        float sph, cph;
        __sincosf(p4.x, &sph, &cph);  o.x = a4.x * (cph * Ss + sph * Cs);
        __sincosf(p4.y, &sph, &cph);  o.y = a4.y * (cph * Ss + sph * Cs);
        __sincosf(p4.z, &sph, &cph);  o.z = a4.z * (cph * Ss + sph * Cs);
        __sincosf(p4.w, &sph, &cph);  o.w = a4.w * (cph * Ss + sph * Cs);
        const int sbo = blockIdx.x * SB_PER_BLK + sl;
        reinterpret_cast<float4*>(out + sbo * DDIM)[h] = o;
    }
}

extern "C" void kernel_launch(void* const* d_in, const int* in_sizes, int n_in,
                              void* d_out, int out_size)
{
    const float* x    = (const float*)d_in[0];   // (S,B,1,T)
    const float* nlf  = (const float*)d_in[1];   // (S,B,1,1)
    const float* tau  = (const float*)d_in[2];   // (S,B,1,1)
    const float* a    = (const float*)d_in[3];   // (D,1)
    const float* phi  = (const float*)d_in[4];   // (D,1)
    const float* i2pi = (const float*)d_in[5];   // (D,1)
    const float* kT   = (const float*)d_in[6];   // (1,T)
    float* out = (float*)d_out;                  // (S,B,D)

    sinenet_kernel<<<1024 / SB_PER_BLK, 256>>>(x, nlf, tau, a, phi, i2pi, kT, out);
}

// round 14
// speedup vs baseline: 1.0239x; 1.0239x over previous
#include <cuda_runtime.h>

#define TLEN  640
#define DDIM  256
#define NH    64              // distinct harmonics (D / NUM_CH)
#define NWARP 8
#define NT    (TLEN / NWARP)  // 80 samples per warp chunk

typedef unsigned long long u64;

__device__ __forceinline__ u64 pk2(float lo, float hi) {
    u64 r; asm("mov.b64 %0, {%1,%2};" : "=l"(r) : "f"(lo), "f"(hi)); return r;
}
__device__ __forceinline__ void upk2(u64 v, float &lo, float &hi) {
    asm("mov.b64 {%0,%1}, %2;" : "=f"(lo), "=f"(hi) : "l"(v));
}
__device__ __forceinline__ u64 fma2(u64 a, u64 b, u64 c) {
    u64 d; asm("fma.rn.f32x2 %0, %1, %2, %3;" : "=l"(d) : "l"(a), "l"(b), "l"(c)); return d;
}

#define INV2PI 0.15915494309189535f
#define PI2_HI 6.28125f                    // 8-bit mantissa: k*PI2_HI exact for k small
#define PI2_LO 1.9353071795864769e-3f
#define T_WAV  6.25e-05f                   // fl(1/16000), matches reference arange*scalar

// fast mod-2pi + MUFU sincos
__device__ __forceinline__ void fast_sincos_r(float x, float *s, float *c) {
    const float k = rintf(x * INV2PI);
    float r = __fmaf_rn(-k, PI2_HI, x);
    r = __fmaf_rn(-k, PI2_LO, r);
    __sincosf(r, s, c);
}

// Even/odd-packed Goertzel: f32x2 lanes = (even-sample, odd-sample) chains of
// the SAME harmonic at angle 2*delta -> the LDS.128 result {x0,x1},{x2,x3} is
// the FMA operand directly (zero pack MOVs in the main loop).
// Per chain y = s1 - e^{-i2d}s2; combine (R3-validated):
//   conj(y_tot) = e^{-id} conj(y_e) + conj(y_o);  C + iS = e^{i psi} conj(y_tot)
// psi anchored at the chunk's last sample.
// out[sb,dd] = a[dd] * ( cos(phi)*S_h + sin(phi)*C_h ),  h = dd>>2
__global__ __launch_bounds__(256, 6) void sinenet_kernel(
    const float* __restrict__ x,   const float* __restrict__ nlf,
    const float* __restrict__ tau, const float* __restrict__ a,
    const float* __restrict__ phi, const float* __restrict__ i2pi,
    const float* __restrict__ kT,  float* __restrict__ out)
{
    __shared__ __align__(16) float xs[TLEN];
    __shared__ float partS[NWARP][NH], partC[NWARP][NH];

    const int sb  = blockIdx.x;
    const int tid = threadIdx.x;
    const int w   = tid >> 5;
    const int l   = tid & 31;

    // stage x[sb,:] (160 float4 loads; issued first, overlapped by seed math)
    if (tid < TLEN / 4) {
        const float4 v = reinterpret_cast<const float4*>(x + sb * TLEN)[tid];
        reinterpret_cast<float4*>(xs)[tid] = v;
    }

    // ---- per-thread seeds, all fp32 ----
    const float fF   = expf(__fadd_rn(__fmul_rn(nlf[sb], 0.373288f), 5.02654f));
    const float tv   = tau[sb];
    const float om1  = __fmul_rn(i2pi[0], fF);
    const float tshL = __fadd_rn(__fmul_rn((float)(w * NT + (NT - 1)), T_WAV), -tv);

    // base = om1*tshL mod 2pi as hi/lo pair (exact product split + Cody-Waite)
    float bHi, bLo;
    {
        const float p  = __fmul_rn(om1, tshL);
        const float pe = __fmaf_rn(om1, tshL, -p);
        const float k  = rintf(p * INV2PI);
        float r = __fmaf_rn(-k, PI2_HI, p);
        r = __fmaf_rn(-k, PI2_LO, r);
        bHi = r;  bLo = pe;
    }

    float cd[2], sd[2], c2d[2], s2d[2], ce[2], se[2];
    #pragma unroll
    for (int q = 0; q < 2; ++q) {
        const int   h   = l + 32 * q;
        const float Hf  = (float)(h + 1);
        const float omg = __fmul_rn(i2pi[4 * h], fF);     // bit-matches ref's i_f
        const float dlt = omg * T_WAV;
        fast_sincos_r(dlt, &sd[q], &cd[q]);               // combine rotation
        fast_sincos_r(dlt + dlt, &s2d[q], &c2d[q]);       // chain angle 2*delta
        const float eps = __fmaf_rn(-Hf, om1, omg);       // exact residual
        // psi = Hf*(bHi+bLo) + eps*tshL, Cody-Waite reduced mod 2pi
        const float p   = Hf * bHi;
        const float pe  = __fmaf_rn(Hf, bHi, -p);
        const float plo = __fmaf_rn(Hf, bLo, __fmaf_rn(eps, tshL, pe));
        const float k   = rintf(p * INV2PI);
        float r = __fmaf_rn(-k, PI2_HI, p);
        r = __fmaf_rn(-k, PI2_LO, r) + plo;
        __sincosf(r, &se[q], &ce[q]);
    }

    const u64 twoC0 = pk2(c2d[0] + c2d[0], c2d[0] + c2d[0]);
    const u64 twoC1 = pk2(c2d[1] + c2d[1], c2d[1] + c2d[1]);
    const u64 nOne  = pk2(-1.0f, -1.0f);
    u64 s1a = 0ull, s2a = 0ull;   // harmonic l   : {even, odd} chains
    u64 s1b = 0ull, s2b = 0ull;   // harmonic l+32: {even, odd} chains

    __syncthreads();   // xs ready

    // main loop: 1 LDS.128 + 8 packed fma per 4 samples, ZERO pack MOVs
    const ulonglong2* xp = reinterpret_cast<const ulonglong2*>(xs + w * NT);
    #pragma unroll 5
    for (int j = 0; j < NT / 4; ++j) {
        const ulonglong2 xv = xp[j];   // .x={x0,x1}  .y={x2,x3}
        {   const u64 t = fma2(nOne, s2a, xv.x);
            const u64 n = fma2(twoC0, s1a, t);  s2a = s1a; s1a = n; }
        {   const u64 t = fma2(nOne, s2b, xv.x);
            const u64 n = fma2(twoC1, s1b, t);  s2b = s1b; s1b = n; }
        {   const u64 t = fma2(nOne, s2a, xv.y);
            const u64 n = fma2(twoC0, s1a, t);  s2a = s1a; s1a = n; }
        {   const u64 t = fma2(nOne, s2b, xv.y);
            const u64 n = fma2(twoC1, s1b, t);  s2b = s1b; s1b = n; }
    }

    // extraction per harmonic: even/odd sub-chains then R3 combine
    #pragma unroll
    for (int q = 0; q < 2; ++q) {
        float Ae, Ao, Be, Bo;
        if (q == 0) { upk2(s1a, Ae, Ao); upk2(s2a, Be, Bo); }
        else        { upk2(s1b, Ae, Ao); upk2(s2b, Be, Bo); }
        const float ReE = __fmaf_rn(-c2d[q], Be, Ae);
        const float ImE = s2d[q] * Be;
        const float ReO = __fmaf_rn(-c2d[q], Bo, Ao);
        const float ImO = s2d[q] * Bo;
        // conj(y_tot) = e^{-id} conj(y_e) + conj(y_o)
        const float ReT = ReO + __fmaf_rn(ReE, cd[q], -ImE * sd[q]);
        const float ImT = ImO + __fmaf_rn(ReE, sd[q],  ImE * cd[q]);
        const int h = l + 32 * q;
        partS[w][h] = se[q] * ReT - ce[q] * ImT;
        partC[w][h] = ce[q] * ReT + se[q] * ImT;
    }
    __syncthreads();

    // fused reduce + epilogue: 64 threads, one harmonic each -> float4 out
    if (tid < NH) {
        const int h = tid;
        float Ss = 0.0f, Cs = 0.0f;
        #pragma unroll
        for (int ww = 0; ww < NWARP; ++ww) {
            Ss += partS[ww][h];
            Cs += partC[ww][h];
        }
        const float4 a4 = reinterpret_cast<const float4*>(a)[h];
        const float4 p4 = reinterpret_cast<const float4*>(phi)[h];
        float4 o;
        float sph, cph;
        __sincosf(p4.x, &sph, &cph);  o.x = a4.x * (cph * Ss + sph * Cs);
        __sincosf(p4.y, &sph, &cph);  o.y = a4.y * (cph * Ss + sph * Cs);
        __sincosf(p4.z, &sph, &cph);  o.z = a4.z * (cph * Ss + sph * Cs);
        __sincosf(p4.w, &sph, &cph);  o.w = a4.w * (cph * Ss + sph * Cs);
        reinterpret_cast<float4*>(out + sb * DDIM)[h] = o;
    }
}

extern "C" void kernel_launch(void* const* d_in, const int* in_sizes, int n_in,
                              void* d_out, int out_size)
{
    const float* x    = (const float*)d_in[0];   // (S,B,1,T)
    const float* nlf  = (const float*)d_in[1];   // (S,B,1,1)
    const float* tau  = (const float*)d_in[2];   // (S,B,1,1)
    const float* a    = (const float*)d_in[3];   // (D,1)
    const float* phi  = (const float*)d_in[4];   // (D,1)
    const float* i2pi = (const float*)d_in[5];   // (D,1)
    const float* kT   = (const float*)d_in[6];   // (1,T)
    float* out = (float*)d_out;                  // (S,B,D)

    sinenet_kernel<<<1024, 256>>>(x, nlf, tau, a, phi, i2pi, kT, out);
}